// round 1
// baseline (speedup 1.0000x reference)
#include <cuda_runtime.h>

#define NN  400
#define FF  240
#define CC  32
#define LL  1440

// ---------------- scratch (device globals; no allocation allowed) ----------------
__device__ __align__(16) float g_U[NN*CC];
__device__ __align__(16) float g_V[NN*CC];
__device__ __align__(16) float g_aggi[NN*CC];
__device__ __align__(16) float g_aggj[NN*CC];
__device__ __align__(16) float g_e2 [NN*NN];
__device__ __align__(16) float g_e2T[NN*NN];
__device__ __align__(16) float g_aT [NN*NN];
__device__ __align__(16) float g_eT [NN*NN];
__device__ __align__(16) float g_x2[NN*FF];
__device__ __align__(16) float g_x3[NN*FF];

// ---------------- 400x400 transpose ----------------
__global__ void transpose_kernel(const float* __restrict__ src, float* __restrict__ dst)
{
    __shared__ float tile[32][33];
    int x = blockIdx.x * 32 + threadIdx.x;
    int y = blockIdx.y * 32 + threadIdx.y;
#pragma unroll
    for (int dy = 0; dy < 32; dy += 8)
        if (x < NN && (y + dy) < NN)
            tile[threadIdx.y + dy][threadIdx.x] = src[(y + dy) * NN + x];
    __syncthreads();
    int x2 = blockIdx.y * 32 + threadIdx.x;
    int y2 = blockIdx.x * 32 + threadIdx.y;
#pragma unroll
    for (int dy = 0; dy < 32; dy += 8)
        if (x2 < NN && (y2 + dy) < NN)
            dst[(y2 + dy) * NN + x2] = tile[threadIdx.x][threadIdx.y + dy];
}

// ---------------- U = x @ sw[0:240], V = x @ sw[240:480] ----------------
// grid 50 blocks (8 rows each), 64 threads (warp0 -> U channels, warp1 -> V channels)
__global__ void uv_kernel(const float* __restrict__ x, const float* __restrict__ sw,
                          float* __restrict__ U, float* __restrict__ V)
{
    __shared__ __align__(16) float xs[FF * 8];   // transposed: xs[f*8 + r]
    int r0 = blockIdx.x * 8;
    for (int idx = threadIdx.x; idx < FF * 8; idx += 64) {
        int f = idx >> 3, r = idx & 7;
        xs[idx] = x[(r0 + r) * FF + f];
    }
    __syncthreads();

    int half = threadIdx.x >> 5;
    int c    = threadIdx.x & 31;
    const float* w = sw + half * FF * CC;

    float acc[8];
#pragma unroll
    for (int r = 0; r < 8; r++) acc[r] = 0.f;

    const float4* xs4 = (const float4*)xs;
    for (int f = 0; f < FF; f++) {
        float wf = __ldg(&w[f * CC + c]);
        float4 a0 = xs4[f * 2 + 0];
        float4 a1 = xs4[f * 2 + 1];
        acc[0] = fmaf(a0.x, wf, acc[0]);
        acc[1] = fmaf(a0.y, wf, acc[1]);
        acc[2] = fmaf(a0.z, wf, acc[2]);
        acc[3] = fmaf(a0.w, wf, acc[3]);
        acc[4] = fmaf(a1.x, wf, acc[4]);
        acc[5] = fmaf(a1.y, wf, acc[5]);
        acc[6] = fmaf(a1.z, wf, acc[6]);
        acc[7] = fmaf(a1.w, wf, acc[7]);
    }
    float* dst = half ? V : U;
#pragma unroll
    for (int r = 0; r < 8; r++)
        dst[(r0 + r) * CC + c] = acc[r];
}

// ---------------- pair pass: thread-per-pair, 32 channels in registers ----------------
// Used both i-major (agg_i + e_out; own=U, oth=V) and j-major (agg_j; own=V, oth=U).
// pre[c] = own[b,c]+sb[c] + oth[t,c] + eF[b,t]*we[c] + eR[b,t]*wet[c]
// s = relu(pre) * amat[b,t];  gate = sigmoid(s.gw + gb);  agg[b] += gate*s
template<bool WRITE_E>
__global__ __launch_bounds__(128) void pair_pass_kernel(
    const float*  __restrict__ own_tab,
    const float4* __restrict__ oth4,
    const float*  __restrict__ eF,
    const float*  __restrict__ eR,
    const float*  __restrict__ amat,
    const float*  __restrict__ we,
    const float*  __restrict__ wet,
    const float*  __restrict__ sb,
    const float*  __restrict__ gw,
    const float*  __restrict__ gb,
    const float*  __restrict__ ew,
    const float*  __restrict__ eb,
    float* __restrict__ agg_out,
    float* __restrict__ e_out)
{
    __shared__ float4 cw4[CC];          // {own[c]+sb[c], we[c], wet[c], gw[c]}
    __shared__ float  cew[CC];
    __shared__ float  red[128 * CC];

    int b   = blockIdx.x;
    int tid = threadIdx.x;
    if (tid < CC) {
        int c = tid;
        cw4[c] = make_float4(own_tab[b * CC + c] + sb[c], we[c], wet[c], gw[c]);
        if (WRITE_E) cew[c] = ew[c];
    }
    __syncthreads();

    float gbias = gb[0];
    float ebias = WRITE_E ? eb[0] : 0.f;

    float agg[CC];
#pragma unroll
    for (int c = 0; c < CC; c++) agg[c] = 0.f;

    const float* eFrow = eF   + b * NN;
    const float* eRrow = eR   + b * NN;
    const float* arow  = amat + b * NN;

    for (int t = tid; t < NN; t += 128) {
        float eij = __ldg(&eFrow[t]);
        float eji = __ldg(&eRrow[t]);
        float am  = __ldg(&arow[t]);
        float ai = 0.f, eo = 0.f;
        float s[CC];
#pragma unroll
        for (int c4 = 0; c4 < CC / 4; c4++) {
            float4 v = __ldg(&oth4[t * (CC / 4) + c4]);
            float vv[4] = {v.x, v.y, v.z, v.w};
#pragma unroll
            for (int u = 0; u < 4; u++) {
                int c = c4 * 4 + u;
                float4 w = cw4[c];
                float pre = w.x + vv[u];
                pre = fmaf(eij, w.y, pre);
                pre = fmaf(eji, w.z, pre);
                float sv = fmaxf(pre, 0.f) * am;
                s[c] = sv;
                ai = fmaf(sv, w.w, ai);
                if (WRITE_E) eo = fmaf(sv, cew[c], eo);
            }
        }
        float att = 1.f / (1.f + __expf(-(ai + gbias)));
        if (WRITE_E) e_out[b * NN + t] = eo + ebias;
#pragma unroll
        for (int c = 0; c < CC; c++) agg[c] = fmaf(att, s[c], agg[c]);
    }

#pragma unroll
    for (int c = 0; c < CC; c++) red[tid * CC + c] = agg[c];
    __syncthreads();
    if (tid < CC) {
        float sum = 0.f;
        for (int t = 0; t < 128; t++) sum += red[t * CC + tid];
        agg_out[b * CC + tid] = sum;
    }
}

// ---------------- node model: out = [x | agg_i | agg_j] @ nw + nb ----------------
// grid 50 blocks (8 rows), 240 threads (one output feature each)
__global__ void node_gemm_kernel(const float* __restrict__ x,
                                 const float* __restrict__ aggi,
                                 const float* __restrict__ aggj,
                                 const float* __restrict__ nw,
                                 const float* __restrict__ nb,
                                 float* __restrict__ out)
{
    const int K = FF + 2 * CC;                 // 304
    __shared__ __align__(16) float cs[304 * 8]; // transposed: cs[k*8 + r]
    int r0 = blockIdx.x * 8;
    for (int idx = threadIdx.x; idx < K * 8; idx += 240) {
        int k = idx >> 3, r = idx & 7;
        int row = r0 + r;
        float v;
        if (k < FF)            v = x[row * FF + k];
        else if (k < FF + CC)  v = aggi[row * CC + (k - FF)];
        else                   v = aggj[row * CC + (k - FF - CC)];
        cs[idx] = v;
    }
    __syncthreads();

    int f = threadIdx.x;
    float bias = nb[f];
    float acc[8];
#pragma unroll
    for (int r = 0; r < 8; r++) acc[r] = bias;

    const float4* cs4 = (const float4*)cs;
    for (int k = 0; k < K; k++) {
        float wf = __ldg(&nw[k * FF + f]);
        float4 a0 = cs4[k * 2 + 0];
        float4 a1 = cs4[k * 2 + 1];
        acc[0] = fmaf(a0.x, wf, acc[0]);
        acc[1] = fmaf(a0.y, wf, acc[1]);
        acc[2] = fmaf(a0.z, wf, acc[2]);
        acc[3] = fmaf(a0.w, wf, acc[3]);
        acc[4] = fmaf(a1.x, wf, acc[4]);
        acc[5] = fmaf(a1.y, wf, acc[5]);
        acc[6] = fmaf(a1.z, wf, acc[6]);
        acc[7] = fmaf(a1.w, wf, acc[7]);
    }
#pragma unroll
    for (int r = 0; r < 8; r++)
        out[(r0 + r) * FF + f] = acc[r];
}

// ---------------- final dense: out = x @ dw + db  (400x240 @ 240x1440) ----------------
// grid (25 row-tiles of 16, 5 col-tiles of 288), 288 threads
__global__ void dense_kernel(const float* __restrict__ x,
                             const float* __restrict__ dw,
                             const float* __restrict__ db,
                             float* __restrict__ out)
{
    __shared__ __align__(16) float xs[FF * 16];  // transposed: xs[k*16 + r]
    int r0 = blockIdx.x * 16;
    for (int idx = threadIdx.x; idx < FF * 16; idx += 288) {
        int k = idx >> 4, r = idx & 15;
        xs[idx] = x[(r0 + r) * FF + k];
    }
    __syncthreads();

    int col = blockIdx.y * 288 + threadIdx.x;
    float bias = db[col];
    float acc[16];
#pragma unroll
    for (int r = 0; r < 16; r++) acc[r] = bias;

    const float4* xs4 = (const float4*)xs;
    for (int k = 0; k < FF; k++) {
        float wf = __ldg(&dw[k * LL + col]);
        float4 a0 = xs4[k * 4 + 0];
        float4 a1 = xs4[k * 4 + 1];
        float4 a2 = xs4[k * 4 + 2];
        float4 a3 = xs4[k * 4 + 3];
        acc[ 0] = fmaf(a0.x, wf, acc[ 0]);
        acc[ 1] = fmaf(a0.y, wf, acc[ 1]);
        acc[ 2] = fmaf(a0.z, wf, acc[ 2]);
        acc[ 3] = fmaf(a0.w, wf, acc[ 3]);
        acc[ 4] = fmaf(a1.x, wf, acc[ 4]);
        acc[ 5] = fmaf(a1.y, wf, acc[ 5]);
        acc[ 6] = fmaf(a1.z, wf, acc[ 6]);
        acc[ 7] = fmaf(a1.w, wf, acc[ 7]);
        acc[ 8] = fmaf(a2.x, wf, acc[ 8]);
        acc[ 9] = fmaf(a2.y, wf, acc[ 9]);
        acc[10] = fmaf(a2.z, wf, acc[10]);
        acc[11] = fmaf(a2.w, wf, acc[11]);
        acc[12] = fmaf(a3.x, wf, acc[12]);
        acc[13] = fmaf(a3.y, wf, acc[13]);
        acc[14] = fmaf(a3.z, wf, acc[14]);
        acc[15] = fmaf(a3.w, wf, acc[15]);
    }
#pragma unroll
    for (int r = 0; r < 16; r++)
        out[(r0 + r) * LL + col] = acc[r];
}

// ---------------- launch ----------------
extern "C" void kernel_launch(void* const* d_in, const int* in_sizes, int n_in,
                              void* d_out, int out_size)
{
    const float* x      = (const float*)d_in[0];
    const float* a      = (const float*)d_in[1];
    const float* e      = (const float*)d_in[2];
    const float* c1_sw  = (const float*)d_in[3];
    const float* c1_sb  = (const float*)d_in[4];
    const float* c1_aiw = (const float*)d_in[5];
    const float* c1_aib = (const float*)d_in[6];
    const float* c1_ajw = (const float*)d_in[7];
    const float* c1_ajb = (const float*)d_in[8];
    const float* c1_nw  = (const float*)d_in[9];
    const float* c1_nb  = (const float*)d_in[10];
    const float* c1_ew  = (const float*)d_in[11];
    const float* c1_eb  = (const float*)d_in[12];
    const float* c2_sw  = (const float*)d_in[13];
    const float* c2_sb  = (const float*)d_in[14];
    const float* c2_aiw = (const float*)d_in[15];
    const float* c2_aib = (const float*)d_in[16];
    const float* c2_ajw = (const float*)d_in[17];
    const float* c2_ajb = (const float*)d_in[18];
    const float* c2_nw  = (const float*)d_in[19];
    const float* c2_nb  = (const float*)d_in[20];
    const float* c2_ew  = (const float*)d_in[21];
    const float* c2_eb  = (const float*)d_in[22];
    const float* dw     = (const float*)d_in[23];
    const float* db     = (const float*)d_in[24];
    float* out = (float*)d_out;

    float *pU, *pV, *pAi, *pAj, *pE2, *pE2T, *pAT, *pET, *pX2, *pX3;
    cudaGetSymbolAddress((void**)&pU,   g_U);
    cudaGetSymbolAddress((void**)&pV,   g_V);
    cudaGetSymbolAddress((void**)&pAi,  g_aggi);
    cudaGetSymbolAddress((void**)&pAj,  g_aggj);
    cudaGetSymbolAddress((void**)&pE2,  g_e2);
    cudaGetSymbolAddress((void**)&pE2T, g_e2T);
    cudaGetSymbolAddress((void**)&pAT,  g_aT);
    cudaGetSymbolAddress((void**)&pET,  g_eT);
    cudaGetSymbolAddress((void**)&pX2,  g_x2);
    cudaGetSymbolAddress((void**)&pX3,  g_x3);

    dim3 tb(32, 8), tg(13, 13);
    transpose_kernel<<<tg, tb>>>(a, pAT);
    transpose_kernel<<<tg, tb>>>(e, pET);

    // ---- layer 1 ----
    uv_kernel<<<50, 64>>>(x, c1_sw, pU, pV);
    pair_pass_kernel<true><<<NN, 128>>>(pU, (const float4*)pV, e, pET, a,
        c1_sw + 480 * CC, c1_sw + 481 * CC, c1_sb,
        c1_aiw, c1_aib, c1_ew, c1_eb, pAi, pE2);
    pair_pass_kernel<false><<<NN, 128>>>(pV, (const float4*)pU, pET, e, pAT,
        c1_sw + 480 * CC, c1_sw + 481 * CC, c1_sb,
        c1_ajw, c1_ajb, nullptr, nullptr, pAj, nullptr);
    node_gemm_kernel<<<50, 240>>>(x, pAi, pAj, c1_nw, c1_nb, pX2);
    transpose_kernel<<<tg, tb>>>(pE2, pE2T);

    // ---- layer 2 (e_out not needed downstream) ----
    uv_kernel<<<50, 64>>>(pX2, c2_sw, pU, pV);
    pair_pass_kernel<false><<<NN, 128>>>(pU, (const float4*)pV, pE2, pE2T, a,
        c2_sw + 480 * CC, c2_sw + 481 * CC, c2_sb,
        c2_aiw, c2_aib, nullptr, nullptr, pAi, nullptr);
    pair_pass_kernel<false><<<NN, 128>>>(pV, (const float4*)pU, pE2T, pE2, pAT,
        c2_sw + 480 * CC, c2_sw + 481 * CC, c2_sb,
        c2_ajw, c2_ajb, nullptr, nullptr, pAj, nullptr);
    node_gemm_kernel<<<50, 240>>>(pX2, pAi, pAj, c2_nw, c2_nb, pX3);

    // ---- final dense ----
    dense_kernel<<<dim3(25, 5), 288>>>(pX3, dw, db, out);
}

// round 2
// speedup vs baseline: 1.2967x; 1.2967x over previous
#include <cuda_runtime.h>

#define NN  400
#define FF  240
#define CC  32
#define LL  1440

// ---------------- scratch (device globals; no allocation allowed) ----------------
__device__ __align__(16) float g_U[NN*CC];
__device__ __align__(16) float g_V[NN*CC];
__device__ __align__(16) float g_aggi[NN*CC];
__device__ __align__(16) float g_aggj[NN*CC];
__device__ __align__(16) float g_e2 [NN*NN];
__device__ __align__(16) float g_e2T[NN*NN];
__device__ __align__(16) float g_aT [NN*NN];
__device__ __align__(16) float g_eT [NN*NN];
__device__ __align__(16) float g_x2[NN*FF];
__device__ __align__(16) float g_x3[NN*FF];

// ---------------- fused 400x400 transposes: z=0 -> a->aT, z=1 -> e->eT -------------
__global__ void transpose2_kernel(const float* __restrict__ a, float* __restrict__ aT,
                                  const float* __restrict__ e, float* __restrict__ eT)
{
    const float* src = blockIdx.z ? e : a;
    float*       dst = blockIdx.z ? eT : aT;
    __shared__ float tile[32][33];
    int x = blockIdx.x * 32 + threadIdx.x;
    int y = blockIdx.y * 32 + threadIdx.y;
#pragma unroll
    for (int dy = 0; dy < 32; dy += 8)
        if (x < NN && (y + dy) < NN)
            tile[threadIdx.y + dy][threadIdx.x] = src[(y + dy) * NN + x];
    __syncthreads();
    int x2 = blockIdx.y * 32 + threadIdx.x;
    int y2 = blockIdx.x * 32 + threadIdx.y;
#pragma unroll
    for (int dy = 0; dy < 32; dy += 8)
        if (x2 < NN && (y2 + dy) < NN)
            dst[(y2 + dy) * NN + x2] = tile[threadIdx.x][threadIdx.y + dy];
}

// ---------------- U = x @ sw[0:240], V = x @ sw[240:480] ----------------
// block per row: 64 threads (warp0 -> U channels, warp1 -> V channels), 4 accumulators
__global__ __launch_bounds__(64) void uv_kernel(
    const float* __restrict__ x, const float* __restrict__ sw,
    float* __restrict__ U, float* __restrict__ V)
{
    __shared__ __align__(16) float xs[FF];
    int row = blockIdx.x;
    if (threadIdx.x < FF / 4)
        ((float4*)xs)[threadIdx.x] = ((const float4*)(x + row * FF))[threadIdx.x];
    __syncthreads();

    int half = threadIdx.x >> 5;
    int c    = threadIdx.x & 31;
    const float* w = sw + half * FF * CC + c;

    float a0 = 0.f, a1 = 0.f, a2 = 0.f, a3 = 0.f;
#pragma unroll 4
    for (int k = 0; k < FF; k += 4) {
        a0 = fmaf(xs[k + 0], __ldg(&w[(k + 0) * CC]), a0);
        a1 = fmaf(xs[k + 1], __ldg(&w[(k + 1) * CC]), a1);
        a2 = fmaf(xs[k + 2], __ldg(&w[(k + 2) * CC]), a2);
        a3 = fmaf(xs[k + 3], __ldg(&w[(k + 3) * CC]), a3);
    }
    float* dst = half ? V : U;
    dst[row * CC + c] = (a0 + a1) + (a2 + a3);
}

// ---------------- fused pair pass: grid (400, 2); y=0 -> agg_i (+e_out), y=1 -> agg_j
// pre[c] = own[b,c]+sb[c] + oth[t,c] + eF[b,t]*we[c] + eR[b,t]*wet[c]
// s = relu(pre) * am[b,t]; att = sigmoid(s.gw + gb); agg[b] += att*s
__global__ __launch_bounds__(128) void pair_both_kernel(
    const float*  __restrict__ U,
    const float*  __restrict__ V,
    const float*  __restrict__ e,
    const float*  __restrict__ eT,
    const float*  __restrict__ a,
    const float*  __restrict__ aT,
    const float*  __restrict__ we,
    const float*  __restrict__ wet,
    const float*  __restrict__ sb,
    const float*  __restrict__ aiw, const float* __restrict__ aib,
    const float*  __restrict__ ajw, const float* __restrict__ ajb,
    const float*  __restrict__ ew,  const float* __restrict__ eb,
    float* __restrict__ aggi, float* __restrict__ aggj,
    float* __restrict__ e_out, float* __restrict__ e_outT)
{
    __shared__ float4 cw4[CC];            // {own[c]+sb[c], we[c], wet[c], gw[c]}
    __shared__ float  cew[CC];
    __shared__ float  red[128 * (CC + 1)]; // padded: conflict-free
    __shared__ float  part[128];

    int b    = blockIdx.x;
    int side = blockIdx.y;
    int tid  = threadIdx.x;

    const float*  own  = side ? V : U;
    const float4* oth4 = (const float4*)(side ? U : V);
    const float*  eFrow = (side ? eT : e)  + b * NN;
    const float*  eRrow = (side ? e  : eT) + b * NN;
    const float*  arow  = (side ? aT : a)  + b * NN;
    const float*  gw = side ? ajw : aiw;
    const float*  gb = side ? ajb : aib;
    float* agg_out = side ? aggj : aggi;
    const bool write_e = (side == 0) && (e_out != nullptr);

    if (tid < CC) {
        int c = tid;
        cw4[c] = make_float4(own[b * CC + c] + sb[c], we[c], wet[c], gw[c]);
        cew[c] = write_e ? ew[c] : 0.f;
    }
    __syncthreads();

    float gbias = gb[0];
    float ebias = write_e ? eb[0] : 0.f;

    float agg[CC];
#pragma unroll
    for (int c = 0; c < CC; c++) agg[c] = 0.f;

    for (int t = tid; t < NN; t += 128) {
        float eij = __ldg(&eFrow[t]);
        float eji = __ldg(&eRrow[t]);
        float am  = __ldg(&arow[t]);
        float ai = 0.f, eo = 0.f;
        float s[CC];
#pragma unroll
        for (int c4 = 0; c4 < CC / 4; c4++) {
            float4 v = __ldg(&oth4[t * (CC / 4) + c4]);
            float vv[4] = {v.x, v.y, v.z, v.w};
#pragma unroll
            for (int u = 0; u < 4; u++) {
                int c = c4 * 4 + u;
                float4 w = cw4[c];
                float pre = w.x + vv[u];
                pre = fmaf(eij, w.y, pre);
                pre = fmaf(eji, w.z, pre);
                float sv = fmaxf(pre, 0.f) * am;
                s[c] = sv;
                ai = fmaf(sv, w.w, ai);
                eo = fmaf(sv, cew[c], eo);
            }
        }
        float att = 1.f / (1.f + __expf(-(ai + gbias)));
        if (write_e) {
            float ev = eo + ebias;
            e_out[b * NN + t] = ev;
            e_outT[t * NN + b] = ev;
        }
#pragma unroll
        for (int c = 0; c < CC; c++) agg[c] = fmaf(att, s[c], agg[c]);
    }

    // conflict-free two-phase reduction over 128 threads
#pragma unroll
    for (int c = 0; c < CC; c++) red[tid * (CC + 1) + c] = agg[c];
    __syncthreads();
    {
        int c = tid & 31;
        int g = tid >> 5;                 // 4 groups of 32 t's
        float sum = 0.f;
#pragma unroll
        for (int u = 0; u < 32; u++)
            sum += red[(g * 32 + u) * (CC + 1) + c];
        part[tid] = sum;
    }
    __syncthreads();
    if (tid < CC)
        agg_out[b * CC + tid] = (part[tid] + part[32 + tid]) + (part[64 + tid] + part[96 + tid]);
}

// ---------------- node model: out = [x | agg_i | agg_j] @ nw + nb ----------------
// grid 50 (8 rows each), 480 threads = 240 features x 2 K-halves
__global__ __launch_bounds__(480) void node_gemm_kernel(
    const float* __restrict__ x,
    const float* __restrict__ aggi,
    const float* __restrict__ aggj,
    const float* __restrict__ nw,
    const float* __restrict__ nb,
    float* __restrict__ out)
{
    const int K = FF + 2 * CC;                  // 304
    const int KH = K / 2;                       // 152
    __shared__ __align__(16) float cs[304 * 8]; // transposed: cs[k*8 + r]
    __shared__ float pred[8 * FF];              // khalf=1 partials
    int r0 = blockIdx.x * 8;
    for (int idx = threadIdx.x; idx < K * 8; idx += 480) {
        int k = idx >> 3, r = idx & 7;
        int row = r0 + r;
        float v;
        if (k < FF)            v = x[row * FF + k];
        else if (k < FF + CC)  v = aggi[row * CC + (k - FF)];
        else                   v = aggj[row * CC + (k - FF - CC)];
        cs[idx] = v;
    }
    __syncthreads();

    int f     = threadIdx.x % FF;
    int khalf = threadIdx.x / FF;
    int kbeg  = khalf * KH;

    float acc[8];
#pragma unroll
    for (int r = 0; r < 8; r++) acc[r] = 0.f;

    const float4* cs4 = (const float4*)cs;
    for (int k = kbeg; k < kbeg + KH; k++) {
        float wf = __ldg(&nw[k * FF + f]);
        float4 a0 = cs4[k * 2 + 0];
        float4 a1 = cs4[k * 2 + 1];
        acc[0] = fmaf(a0.x, wf, acc[0]);
        acc[1] = fmaf(a0.y, wf, acc[1]);
        acc[2] = fmaf(a0.z, wf, acc[2]);
        acc[3] = fmaf(a0.w, wf, acc[3]);
        acc[4] = fmaf(a1.x, wf, acc[4]);
        acc[5] = fmaf(a1.y, wf, acc[5]);
        acc[6] = fmaf(a1.z, wf, acc[6]);
        acc[7] = fmaf(a1.w, wf, acc[7]);
    }
    if (khalf == 1) {
#pragma unroll
        for (int r = 0; r < 8; r++) pred[r * FF + f] = acc[r];
    }
    __syncthreads();
    if (khalf == 0) {
        float bias = nb[f];
#pragma unroll
        for (int r = 0; r < 8; r++)
            out[(r0 + r) * FF + f] = acc[r] + pred[r * FF + f] + bias;
    }
}

// ---------------- final dense: out = x @ dw + db  (400x240 @ 240x1440) ----------------
__global__ __launch_bounds__(288) void dense_kernel(
    const float* __restrict__ x,
    const float* __restrict__ dw,
    const float* __restrict__ db,
    float* __restrict__ out)
{
    __shared__ __align__(16) float xs[FF * 16];  // transposed: xs[k*16 + r]
    int r0 = blockIdx.x * 16;
    for (int idx = threadIdx.x; idx < FF * 16; idx += 288) {
        int k = idx >> 4, r = idx & 15;
        xs[idx] = x[(r0 + r) * FF + k];
    }
    __syncthreads();

    int col = blockIdx.y * 288 + threadIdx.x;
    float bias = db[col];
    float acc[16];
#pragma unroll
    for (int r = 0; r < 16; r++) acc[r] = bias;

    const float4* xs4 = (const float4*)xs;
    for (int k = 0; k < FF; k++) {
        float wf = __ldg(&dw[k * LL + col]);
        float4 a0 = xs4[k * 4 + 0];
        float4 a1 = xs4[k * 4 + 1];
        float4 a2 = xs4[k * 4 + 2];
        float4 a3 = xs4[k * 4 + 3];
        acc[ 0] = fmaf(a0.x, wf, acc[ 0]);
        acc[ 1] = fmaf(a0.y, wf, acc[ 1]);
        acc[ 2] = fmaf(a0.z, wf, acc[ 2]);
        acc[ 3] = fmaf(a0.w, wf, acc[ 3]);
        acc[ 4] = fmaf(a1.x, wf, acc[ 4]);
        acc[ 5] = fmaf(a1.y, wf, acc[ 5]);
        acc[ 6] = fmaf(a1.z, wf, acc[ 6]);
        acc[ 7] = fmaf(a1.w, wf, acc[ 7]);
        acc[ 8] = fmaf(a2.x, wf, acc[ 8]);
        acc[ 9] = fmaf(a2.y, wf, acc[ 9]);
        acc[10] = fmaf(a2.z, wf, acc[10]);
        acc[11] = fmaf(a2.w, wf, acc[11]);
        acc[12] = fmaf(a3.x, wf, acc[12]);
        acc[13] = fmaf(a3.y, wf, acc[13]);
        acc[14] = fmaf(a3.z, wf, acc[14]);
        acc[15] = fmaf(a3.w, wf, acc[15]);
    }
#pragma unroll
    for (int r = 0; r < 16; r++)
        out[(r0 + r) * LL + col] = acc[r];
}

// ---------------- launch ----------------
extern "C" void kernel_launch(void* const* d_in, const int* in_sizes, int n_in,
                              void* d_out, int out_size)
{
    const float* x      = (const float*)d_in[0];
    const float* a      = (const float*)d_in[1];
    const float* e      = (const float*)d_in[2];
    const float* c1_sw  = (const float*)d_in[3];
    const float* c1_sb  = (const float*)d_in[4];
    const float* c1_aiw = (const float*)d_in[5];
    const float* c1_aib = (const float*)d_in[6];
    const float* c1_ajw = (const float*)d_in[7];
    const float* c1_ajb = (const float*)d_in[8];
    const float* c1_nw  = (const float*)d_in[9];
    const float* c1_nb  = (const float*)d_in[10];
    const float* c1_ew  = (const float*)d_in[11];
    const float* c1_eb  = (const float*)d_in[12];
    const float* c2_sw  = (const float*)d_in[13];
    const float* c2_sb  = (const float*)d_in[14];
    const float* c2_aiw = (const float*)d_in[15];
    const float* c2_aib = (const float*)d_in[16];
    const float* c2_ajw = (const float*)d_in[17];
    const float* c2_ajb = (const float*)d_in[18];
    const float* c2_nw  = (const float*)d_in[19];
    const float* c2_nb  = (const float*)d_in[20];
    const float* c2_ew  = (const float*)d_in[21];
    const float* c2_eb  = (const float*)d_in[22];
    const float* dw     = (const float*)d_in[23];
    const float* db     = (const float*)d_in[24];
    float* out = (float*)d_out;

    float *pU, *pV, *pAi, *pAj, *pE2, *pE2T, *pAT, *pET, *pX2, *pX3;
    cudaGetSymbolAddress((void**)&pU,   g_U);
    cudaGetSymbolAddress((void**)&pV,   g_V);
    cudaGetSymbolAddress((void**)&pAi,  g_aggi);
    cudaGetSymbolAddress((void**)&pAj,  g_aggj);
    cudaGetSymbolAddress((void**)&pE2,  g_e2);
    cudaGetSymbolAddress((void**)&pE2T, g_e2T);
    cudaGetSymbolAddress((void**)&pAT,  g_aT);
    cudaGetSymbolAddress((void**)&pET,  g_eT);
    cudaGetSymbolAddress((void**)&pX2,  g_x2);
    cudaGetSymbolAddress((void**)&pX3,  g_x3);

    // 1. fused transposes (a->aT, e->eT)
    transpose2_kernel<<<dim3(13, 13, 2), dim3(32, 8)>>>(a, pAT, e, pET);

    // ---- layer 1 ----
    uv_kernel<<<NN, 64>>>(x, c1_sw, pU, pV);
    pair_both_kernel<<<dim3(NN, 2), 128>>>(pU, pV, e, pET, a, pAT,
        c1_sw + 480 * CC, c1_sw + 481 * CC, c1_sb,
        c1_aiw, c1_aib, c1_ajw, c1_ajb, c1_ew, c1_eb,
        pAi, pAj, pE2, pE2T);
    node_gemm_kernel<<<50, 480>>>(x, pAi, pAj, c1_nw, c1_nb, pX2);

    // ---- layer 2 (e_out not needed downstream) ----
    uv_kernel<<<NN, 64>>>(pX2, c2_sw, pU, pV);
    pair_both_kernel<<<dim3(NN, 2), 128>>>(pU, pV, pE2, pE2T, a, pAT,
        c2_sw + 480 * CC, c2_sw + 481 * CC, c2_sb,
        c2_aiw, c2_aib, c2_ajw, c2_ajb, nullptr, nullptr,
        pAi, pAj, nullptr, nullptr);
    node_gemm_kernel<<<50, 480>>>(pX2, pAi, pAj, c2_nw, c2_nb, pX3);

    // ---- final dense ----
    dense_kernel<<<dim3(25, 5), 288>>>(pX3, dw, db, out);
}